// round 9
// baseline (speedup 1.0000x reference)
#include <cuda_runtime.h>
#include <math.h>
#include <stdint.h>

#define N_NODES 100000
#define FEAT    256
#define RANK    64
#define HIDD    512
#define OUTD    256
#define NEDGE   200000
#define KE      3

// ---------------- scratch (device globals; no allocations allowed) ----------
__device__ __align__(16) float g_emb_new[N_NODES * RANK];
__device__ __align__(16) float g_hid[N_NODES * HIDD];
__device__ __align__(16) float g_emb2[N_NODES * OUTD];
__device__ __align__(16) float g_sum_c1[N_NODES * RANK];
__device__ __align__(16) float g_sum_s[N_NODES * OUTD];
__device__ __align__(16) float g_emb_r[N_NODES * FEAT];      // tf32-rounded emb
__device__ __align__(16) float g_wp_r[FEAT * RANK];          // rounded weights [K,N]
__device__ __align__(16) float g_w2a_r[FEAT * HIDD];
__device__ __align__(16) float g_w2b_r[HIDD * OUTD];
__device__ __align__(16) float g_wq_r[RANK * OUTD];
__device__ __align__(16) float g_bias1[RANK];                // Wp[FEAT]+bp
__device__ __align__(16) float g_bias2[HIDD];                // W2a[FEAT]+b2a
__device__ int   g_deg[N_NODES];
__device__ float g_dscale[N_NODES];
__device__ float g_invdeg[N_NODES];

__device__ __forceinline__ float tf32r(float x) {
    uint32_t r;
    asm("cvt.rna.tf32.f32 %0, %1;" : "=r"(r) : "f"(x));
    return __uint_as_float(r);
}
__device__ __forceinline__ uint32_t tf32u(float x) {
    uint32_t r;
    asm("cvt.rna.tf32.f32 %0, %1;" : "=r"(r) : "f"(x));
    return r;
}

// ---------------- utility kernels -------------------------------------------
__global__ void zero_kernel() {
    int i = blockIdx.x * blockDim.x + threadIdx.x;
    int stride = gridDim.x * blockDim.x;
    float4 z = make_float4(0.f, 0.f, 0.f, 0.f);
    float4* s4 = (float4*)g_sum_s;
    float4* c4 = (float4*)g_sum_c1;
    for (int t = i; t < N_NODES * OUTD / 4; t += stride) s4[t] = z;
    for (int t = i; t < N_NODES * RANK / 4; t += stride) c4[t] = z;
    for (int t = i; t < N_NODES; t += stride) g_deg[t] = 0;
}

__global__ void deg_kernel(const int* __restrict__ en) {
    int i = blockIdx.x * blockDim.x + threadIdx.x;
    if (i < NEDGE * KE) atomicAdd(&g_deg[en[i]], 1);
}

__global__ void scale_kernel() {
    int v = blockIdx.x * blockDim.x + threadIdx.x;
    if (v < N_NODES) {
        float d = (float)g_deg[v];
        g_dscale[v] = cbrtf(d);
        g_invdeg[v] = 1.0f / d;
    }
}

__global__ void round_tf32_kernel(const float4* __restrict__ src,
                                  float4* __restrict__ dst, int n4) {
    int i = blockIdx.x * blockDim.x + threadIdx.x;
    if (i < n4) {
        float4 v = src[i];
        v.x = tf32r(v.x); v.y = tf32r(v.y); v.z = tf32r(v.z); v.w = tf32r(v.w);
        dst[i] = v;
    }
}

// one kernel: round all weights + combine bias rows
__global__ void wprep_kernel(const float* __restrict__ Wp,  const float* __restrict__ bp,
                             const float* __restrict__ W2a, const float* __restrict__ b2a,
                             const float* __restrict__ W2b,
                             const float* __restrict__ Wq) {
    const int S1 = FEAT * RANK;
    const int S2 = S1 + FEAT * HIDD;
    const int S3 = S2 + HIDD * OUTD;
    const int S4 = S3 + RANK * OUTD;
    const int S5 = S4 + RANK;
    const int S6 = S5 + HIDD;
    int i = blockIdx.x * blockDim.x + threadIdx.x;
    if (i < S1) g_wp_r[i] = tf32r(Wp[i]);
    else if (i < S2) { int j = i - S1; g_w2a_r[j] = tf32r(W2a[j]); }
    else if (i < S3) { int j = i - S2; g_w2b_r[j] = tf32r(W2b[j]); }
    else if (i < S4) { int j = i - S3; g_wq_r[j]  = tf32r(Wq[j]); }
    else if (i < S5) { int j = i - S4; g_bias1[j] = Wp[FEAT * RANK + j] + bp[j]; }
    else if (i < S6) { int j = i - S5; g_bias2[j] = W2a[FEAT * HIDD + j] + b2a[j]; }
}

// ---------------- TF32 tensor-core GEMM v3 -----------------------------------
// Warp tile 64x32 (4x4 m16n8k8). Warps arranged WMW x WNW. BK=16.
// One __syncthreads per k-iter; cp.async double buffered.
// C = act( rowscale[m] * (A@B + D) + bias ), optional relu / tf32-round of C.
template <int WMW, int WNW, int TPB, bool RELU, bool ROUND, bool CVTA>
__global__ __launch_bounds__(TPB) void gemm_v3(
    int M, int N, int K,
    const float* __restrict__ A, const float* __restrict__ B,
    const float* __restrict__ bias,
    const float* __restrict__ D, const float* __restrict__ rowscale,
    float* __restrict__ C)
{
    constexpr int BM = WMW * 64, BN = WNW * 32, BK = 16;
    constexpr int AST = BK + 4;         // 20: frag banks lr*20+lc all distinct
    constexpr int BST = BN + 8;         // frag banks 8*lc+lr all distinct
    constexpr int ATILE = BM * AST;
    constexpr int BTILE = BK * BST;
    constexpr int CA = BM * BK / (4 * TPB);
    constexpr int CB = BK * BN / (4 * TPB);
    static_assert(CA >= 1 && CB >= 1, "tile/thread mismatch");

    extern __shared__ float smem[];
    float* AsB = smem;
    float* BsB = smem + 2 * ATILE;

    int tid = threadIdx.x;
    int warp = tid >> 5, lane = tid & 31;
    int wm = warp / WNW, wn = warp % WNW;
    int lr = lane >> 2, lc = lane & 3;
    int block_m = blockIdx.y * BM, block_n = blockIdx.x * BN;

    float acc[4][4][4];
#pragma unroll
    for (int a = 0; a < 4; a++)
#pragma unroll
        for (int b = 0; b < 4; b++)
#pragma unroll
            for (int c = 0; c < 4; c++) acc[a][b][c] = 0.0f;

    auto load_tiles = [&](int it, float* As, float* Bs) {
#pragma unroll
        for (int i = 0; i < CA; i++) {
            int f = tid + TPB * i;
            int m = f >> 2, q = f & 3;            // 4 x float4 per 16-float row
            int gr = block_m + m;
            uint32_t dst = (uint32_t)__cvta_generic_to_shared(As + m * AST + 4 * q);
            const float* src = A + (size_t)gr * K + it * BK + 4 * q;
            int sz = (gr < M) ? 16 : 0;
            asm volatile("cp.async.cg.shared.global [%0], [%1], 16, %2;"
                         :: "r"(dst), "l"(src), "r"(sz));
        }
#pragma unroll
        for (int i = 0; i < CB; i++) {
            int f = tid + TPB * i;
            int n4 = f % (BN / 4), k = f / (BN / 4);
            uint32_t dst = (uint32_t)__cvta_generic_to_shared(Bs + k * BST + 4 * n4);
            const float* src = B + (size_t)(it * BK + k) * N + block_n + 4 * n4;
            asm volatile("cp.async.cg.shared.global [%0], [%1], 16;"
                         :: "r"(dst), "l"(src));
        }
        asm volatile("cp.async.commit_group;");
    };

    int nIter = K / BK;
    load_tiles(0, AsB, BsB);

    for (int it = 0; it < nIter; ++it) {
        int buf = it & 1;
        asm volatile("cp.async.wait_group 0;");
        __syncthreads();
        if (it + 1 < nIter)
            load_tiles(it + 1, AsB + (buf ^ 1) * ATILE, BsB + (buf ^ 1) * BTILE);
        const float* As = AsB + buf * ATILE;
        const float* Bs = BsB + buf * BTILE;

#pragma unroll
        for (int ks = 0; ks < BK / 8; ks++) {
            int col = ks * 8 + lc;
            uint32_t af[4][4], bfr[4][2];
#pragma unroll
            for (int mt = 0; mt < 4; mt++) {
                const float* ap = As + (wm * 64 + mt * 16 + lr) * AST + col;
                if (CVTA) {
                    af[mt][0] = tf32u(ap[0]);
                    af[mt][1] = tf32u(ap[8 * AST]);
                    af[mt][2] = tf32u(ap[4]);
                    af[mt][3] = tf32u(ap[8 * AST + 4]);
                } else {
                    af[mt][0] = __float_as_uint(ap[0]);
                    af[mt][1] = __float_as_uint(ap[8 * AST]);
                    af[mt][2] = __float_as_uint(ap[4]);
                    af[mt][3] = __float_as_uint(ap[8 * AST + 4]);
                }
            }
#pragma unroll
            for (int nt = 0; nt < 4; nt++) {
                const float* bp = Bs + col * BST + wn * 32 + nt * 8 + lr;
                bfr[nt][0] = __float_as_uint(bp[0]);
                bfr[nt][1] = __float_as_uint(bp[4 * BST]);
            }
#pragma unroll
            for (int mt = 0; mt < 4; mt++)
#pragma unroll
                for (int nt = 0; nt < 4; nt++)
                    asm volatile(
                        "mma.sync.aligned.m16n8k8.row.col.f32.tf32.tf32.f32 "
                        "{%0,%1,%2,%3}, {%4,%5,%6,%7}, {%8,%9}, {%0,%1,%2,%3};"
                        : "+f"(acc[mt][nt][0]), "+f"(acc[mt][nt][1]),
                          "+f"(acc[mt][nt][2]), "+f"(acc[mt][nt][3])
                        : "r"(af[mt][0]), "r"(af[mt][1]), "r"(af[mt][2]), "r"(af[mt][3]),
                          "r"(bfr[nt][0]), "r"(bfr[nt][1]));
        }
        // NOTE: no trailing sync — next iter's sync (after wait) protects buffers
        __syncthreads();
    }

    // epilogue
#pragma unroll
    for (int mt = 0; mt < 4; mt++) {
#pragma unroll
        for (int half = 0; half < 2; half++) {
            int row = block_m + wm * 64 + mt * 16 + lr + half * 8;
            if (row >= M) continue;
            float rs = rowscale ? rowscale[row] : 1.0f;
#pragma unroll
            for (int nt = 0; nt < 4; nt++) {
                int gc = block_n + wn * 32 + nt * 8 + 2 * lc;
                float v0 = acc[mt][nt][half * 2 + 0];
                float v1 = acc[mt][nt][half * 2 + 1];
                if (D) {
                    float2 d = *(const float2*)(D + (size_t)row * N + gc);
                    v0 += d.x; v1 += d.y;
                }
                float b0 = 0.0f, b1 = 0.0f;
                if (bias) { b0 = bias[gc]; b1 = bias[gc + 1]; }
                v0 = rs * v0 + b0;
                v1 = rs * v1 + b1;
                if (RELU) { v0 = fmaxf(v0, 0.0f); v1 = fmaxf(v1, 0.0f); }
                if (ROUND) { v0 = tf32r(v0); v1 = tf32r(v1); }
                *(float2*)(C + (size_t)row * N + gc) = make_float2(v0, v1);
            }
        }
    }
}

constexpr size_t smem_v3(int WMW, int WNW) {
    return (size_t)(2 * (WMW * 64) * 20 + 2 * 16 * (WNW * 32 + 8)) * 4;
}

// ---------------- edge kernel -----------------------------------------------
__device__ __forceinline__ void red4(float* p, float4 v) {
    asm volatile("red.global.add.v4.f32 [%0], {%1,%2,%3,%4};"
                 :: "l"(p), "f"(v.x), "f"(v.y), "f"(v.z), "f"(v.w) : "memory");
}

__global__ __launch_bounds__(256) void edge_kernel(const int* __restrict__ en) {
    int wg = (blockIdx.x * blockDim.x + threadIdx.x) >> 5;
    int lane = threadIdx.x & 31;
    if (wg >= NEDGE) return;
    int v0 = en[wg * 3 + 0];
    int v1 = en[wg * 3 + 1];
    int v2 = en[wg * 3 + 2];
    float d0 = g_dscale[v0], d1 = g_dscale[v1], d2 = g_dscale[v2];

    if (lane < 16) {
        float4 a = *(const float4*)(g_emb_new + (size_t)v0 * RANK + lane * 4);
        float4 b = *(const float4*)(g_emb_new + (size_t)v1 * RANK + lane * 4);
        float4 c = *(const float4*)(g_emb_new + (size_t)v2 * RANK + lane * 4);
        a.x *= d0; a.y *= d0; a.z *= d0; a.w *= d0;
        b.x *= d1; b.y *= d1; b.z *= d1; b.w *= d1;
        c.x *= d2; c.y *= d2; c.z *= d2; c.w *= d2;
        float h0 = 0.5f * d0, h1 = 0.5f * d1, h2 = 0.5f * d2;
        float4 o0 = make_float4(h0 * b.x * c.x, h0 * b.y * c.y, h0 * b.z * c.z, h0 * b.w * c.w);
        float4 o1 = make_float4(h1 * a.x * c.x, h1 * a.y * c.y, h1 * a.z * c.z, h1 * a.w * c.w);
        float4 o2 = make_float4(h2 * a.x * b.x, h2 * a.y * b.y, h2 * a.z * b.z, h2 * a.w * b.w);
        red4(g_sum_c1 + (size_t)v0 * RANK + lane * 4, o0);
        red4(g_sum_c1 + (size_t)v1 * RANK + lane * 4, o1);
        red4(g_sum_c1 + (size_t)v2 * RANK + lane * 4, o2);
    }

    const float4* e0 = (const float4*)(g_emb2) + (size_t)v0 * (OUTD / 4);
    const float4* e1 = (const float4*)(g_emb2) + (size_t)v1 * (OUTD / 4);
    const float4* e2p = (const float4*)(g_emb2) + (size_t)v2 * (OUTD / 4);
#pragma unroll
    for (int t = 0; t < 2; t++) {
        int c4 = lane + t * 32;
        float4 x = e0[c4], y = e1[c4], z = e2p[c4];
        float4 s = make_float4(fmaxf(x.x + y.x + z.x, 0.0f),
                               fmaxf(x.y + y.y + z.y, 0.0f),
                               fmaxf(x.z + y.z + z.z, 0.0f),
                               fmaxf(x.w + y.w + z.w, 0.0f));
        red4(g_sum_s + (size_t)v0 * OUTD + c4 * 4, s);
        red4(g_sum_s + (size_t)v1 * OUTD + c4 * 4, s);
        red4(g_sum_s + (size_t)v2 * OUTD + c4 * 4, s);
    }
}

// ---------------- launch ----------------------------------------------------
extern "C" void kernel_launch(void* const* d_in, const int* in_sizes, int n_in,
                              void* d_out, int out_size) {
    const float* emb = (const float*)d_in[0];
    const int*   en  = (const int*)d_in[1];
    const float* Wp  = (const float*)d_in[2];
    const float* bp  = (const float*)d_in[3];
    const float* W2a = (const float*)d_in[4];
    const float* b2a = (const float*)d_in[5];
    const float* W2b = (const float*)d_in[6];
    const float* b2b = (const float*)d_in[7];
    const float* Wq  = (const float*)d_in[8];
    const float* bq  = (const float*)d_in[9];
    float* out = (float*)d_out;

    float *p_emb_new, *p_hid, *p_emb2, *p_sum_c1, *p_sum_s, *p_invdeg;
    float *p_emb_r, *p_wp_r, *p_w2a_r, *p_w2b_r, *p_wq_r, *p_bias1, *p_bias2;
    cudaGetSymbolAddress((void**)&p_emb_new, g_emb_new);
    cudaGetSymbolAddress((void**)&p_hid,     g_hid);
    cudaGetSymbolAddress((void**)&p_emb2,    g_emb2);
    cudaGetSymbolAddress((void**)&p_sum_c1,  g_sum_c1);
    cudaGetSymbolAddress((void**)&p_sum_s,   g_sum_s);
    cudaGetSymbolAddress((void**)&p_invdeg,  g_invdeg);
    cudaGetSymbolAddress((void**)&p_emb_r,   g_emb_r);
    cudaGetSymbolAddress((void**)&p_wp_r,    g_wp_r);
    cudaGetSymbolAddress((void**)&p_w2a_r,   g_w2a_r);
    cudaGetSymbolAddress((void**)&p_w2b_r,   g_w2b_r);
    cudaGetSymbolAddress((void**)&p_wq_r,    g_wq_r);
    cudaGetSymbolAddress((void**)&p_bias1,   g_bias1);
    cudaGetSymbolAddress((void**)&p_bias2,   g_bias2);

    constexpr size_t SM42 = smem_v3(4, 2);   // 50176
    constexpr size_t SM28 = smem_v3(2, 8);   // 54272
    cudaFuncSetAttribute(gemm_v3<4,2,256,false,false,false>, cudaFuncAttributeMaxDynamicSharedMemorySize, (int)SM42);
    cudaFuncSetAttribute(gemm_v3<2,8,512,true, true, false>, cudaFuncAttributeMaxDynamicSharedMemorySize, (int)SM28);
    cudaFuncSetAttribute(gemm_v3<2,8,512,false,false,false>, cudaFuncAttributeMaxDynamicSharedMemorySize, (int)SM28);
    cudaFuncSetAttribute(gemm_v3<2,8,512,true, false,true >, cudaFuncAttributeMaxDynamicSharedMemorySize, (int)SM28);

    const int M = N_NODES;

    // 1..5: prep (launch #6 = G2 for the ncu window)
    zero_kernel<<<1024, 256>>>();                                   // 1
    deg_kernel<<<(NEDGE * KE + 255) / 256, 256>>>(en);              // 2
    scale_kernel<<<(N_NODES + 255) / 256, 256>>>();                 // 3
    {
        int total = FEAT * RANK + FEAT * HIDD + HIDD * OUTD + RANK * OUTD + RANK + HIDD;
        wprep_kernel<<<(total + 255) / 256, 256>>>(Wp, bp, W2a, b2a, W2b, Wq);  // 4
    }
    {
        int n4 = N_NODES * FEAT / 4;
        round_tf32_kernel<<<(n4 + 255) / 256, 256>>>((const float4*)emb, (float4*)p_emb_r, n4); // 5
    }

    // 6: G2: hid = round(relu(emb @ W2a + bias2))   [BM=128, BN=256, 512 thr]
    gemm_v3<2,8,512,true,true,false><<<dim3(HIDD / 256, (M + 127) / 128), 512, SM28>>>(
        M, HIDD, FEAT, p_emb_r, p_w2a_r, p_bias2, nullptr, nullptr, p_hid);
    // 7: G1: emb_new = emb @ Wp + bias1             [BM=256, BN=64, 256 thr]
    gemm_v3<4,2,256,false,false,false><<<dim3(1, (M + 255) / 256), 256, SM42>>>(
        M, RANK, FEAT, p_emb_r, p_wp_r, p_bias1, nullptr, nullptr, p_emb_new);
    // 8: G3: emb2 = hid @ W2b + b2b                 [BM=128, BN=256, 512 thr]
    gemm_v3<2,8,512,false,false,false><<<dim3(1, (M + 127) / 128), 512, SM28>>>(
        M, OUTD, HIDD, p_hid, p_w2b_r, b2b, nullptr, nullptr, p_emb2);
    // 9: edge scatter
    edge_kernel<<<(NEDGE * 32) / 256, 256>>>(en);
    // 10: G4: out = relu(invdeg * (sum_c1 @ Wq + sum_s) + bq)  [CVTA]
    gemm_v3<2,8,512,true,false,true><<<dim3(1, (M + 127) / 128), 512, SM28>>>(
        M, OUTD, RANK, p_sum_c1, p_wq_r, bq, p_sum_s, p_invdeg, out);
}

// round 10
// speedup vs baseline: 1.0800x; 1.0800x over previous
#include <cuda_runtime.h>
#include <math.h>
#include <stdint.h>

#define N_NODES 100000
#define FEAT    256
#define RANK    64
#define HIDD    512
#define OUTD    256
#define NEDGE   200000
#define KE      3

// ---------------- scratch (device globals; no allocations allowed) ----------
__device__ __align__(16) float g_emb_new[N_NODES * RANK];
__device__ __align__(16) float g_hid[N_NODES * HIDD];
__device__ __align__(16) float g_emb2[N_NODES * OUTD];
__device__ __align__(16) float g_sum_c1[N_NODES * RANK];
__device__ __align__(16) float g_sum_s[N_NODES * OUTD];
__device__ __align__(16) float g_emb_r[N_NODES * FEAT];      // tf32-rounded emb
__device__ __align__(16) float g_wp_r[FEAT * RANK];          // rounded weights [K,N]
__device__ __align__(16) float g_w2a_r[FEAT * HIDD];
__device__ __align__(16) float g_w2b_r[HIDD * OUTD];
__device__ __align__(16) float g_wq_r[RANK * OUTD];
__device__ __align__(16) float g_bias1[RANK];                // Wp[FEAT]+bp
__device__ __align__(16) float g_bias2[HIDD];                // W2a[FEAT]+b2a
__device__ int   g_deg[N_NODES];
__device__ float g_dscale[N_NODES];
__device__ float g_invdeg[N_NODES];

__device__ __forceinline__ float tf32r(float x) {
    uint32_t r;
    asm("cvt.rna.tf32.f32 %0, %1;" : "=r"(r) : "f"(x));
    return __uint_as_float(r);
}
__device__ __forceinline__ uint32_t tf32u(float x) {
    uint32_t r;
    asm("cvt.rna.tf32.f32 %0, %1;" : "=r"(r) : "f"(x));
    return r;
}

// ---------------- utility kernels -------------------------------------------
__global__ void zero_kernel() {
    int i = blockIdx.x * blockDim.x + threadIdx.x;
    int stride = gridDim.x * blockDim.x;
    float4 z = make_float4(0.f, 0.f, 0.f, 0.f);
    float4* s4 = (float4*)g_sum_s;
    float4* c4 = (float4*)g_sum_c1;
    for (int t = i; t < N_NODES * OUTD / 4; t += stride) s4[t] = z;
    for (int t = i; t < N_NODES * RANK / 4; t += stride) c4[t] = z;
    for (int t = i; t < N_NODES; t += stride) g_deg[t] = 0;
}

__global__ void deg_kernel(const int* __restrict__ en) {
    int i = blockIdx.x * blockDim.x + threadIdx.x;
    if (i < NEDGE * KE) atomicAdd(&g_deg[en[i]], 1);
}

__global__ void scale_kernel() {
    int v = blockIdx.x * blockDim.x + threadIdx.x;
    if (v < N_NODES) {
        float d = (float)g_deg[v];
        g_dscale[v] = cbrtf(d);
        g_invdeg[v] = 1.0f / d;
    }
}

__global__ void round_tf32_kernel(const float4* __restrict__ src,
                                  float4* __restrict__ dst, int n4) {
    int i = blockIdx.x * blockDim.x + threadIdx.x;
    if (i < n4) {
        float4 v = src[i];
        v.x = tf32r(v.x); v.y = tf32r(v.y); v.z = tf32r(v.z); v.w = tf32r(v.w);
        dst[i] = v;
    }
}

// one kernel: round all weights + combine bias rows
__global__ void wprep_kernel(const float* __restrict__ Wp,  const float* __restrict__ bp,
                             const float* __restrict__ W2a, const float* __restrict__ b2a,
                             const float* __restrict__ W2b,
                             const float* __restrict__ Wq) {
    const int S1 = FEAT * RANK;
    const int S2 = S1 + FEAT * HIDD;
    const int S3 = S2 + HIDD * OUTD;
    const int S4 = S3 + RANK * OUTD;
    const int S5 = S4 + RANK;
    const int S6 = S5 + HIDD;
    int i = blockIdx.x * blockDim.x + threadIdx.x;
    if (i < S1) g_wp_r[i] = tf32r(Wp[i]);
    else if (i < S2) { int j = i - S1; g_w2a_r[j] = tf32r(W2a[j]); }
    else if (i < S3) { int j = i - S2; g_w2b_r[j] = tf32r(W2b[j]); }
    else if (i < S4) { int j = i - S3; g_wq_r[j]  = tf32r(Wq[j]); }
    else if (i < S5) { int j = i - S4; g_bias1[j] = Wp[FEAT * RANK + j] + bp[j]; }
    else if (i < S6) { int j = i - S5; g_bias2[j] = W2a[FEAT * HIDD + j] + b2a[j]; }
}

// ---------------- TF32 tensor-core GEMM (round-8 pipeline, TPB param) --------
// Warp tile 64x32 (4x4 m16n8k8), warps WMW x WNW, BK=32, double-buffered
// cp.async with wait_group 1 overlap (two syncs/iter — proven structure).
template <int WMW, int WNW, int TPB, bool RELU, bool ROUND, bool CVTA>
__global__ __launch_bounds__(TPB) void gemm_v2(
    int M, int N, int K,
    const float* __restrict__ A, const float* __restrict__ B,
    const float* __restrict__ bias,
    const float* __restrict__ D, const float* __restrict__ rowscale,
    float* __restrict__ C)
{
    constexpr int BM = WMW * 64, BN = WNW * 32, BK = 32;
    constexpr int AST = BK + 4;
    constexpr int BST = BN + 8;
    constexpr int ATILE = BM * AST;
    constexpr int BTILE = BK * BST;
    constexpr int CA = BM * BK / (4 * TPB);
    constexpr int CB = BK * BN / (4 * TPB);
    static_assert(CA >= 1 && CB >= 1, "tile/thread mismatch");
    static_assert(WMW * WNW * 32 == TPB, "warp layout mismatch");

    extern __shared__ float smem[];
    float* AsB = smem;
    float* BsB = smem + 2 * ATILE;

    int tid = threadIdx.x;
    int warp = tid >> 5, lane = tid & 31;
    int wm = warp / WNW, wn = warp % WNW;
    int lr = lane >> 2, lc = lane & 3;
    int block_m = blockIdx.y * BM, block_n = blockIdx.x * BN;

    float acc[4][4][4];
#pragma unroll
    for (int a = 0; a < 4; a++)
#pragma unroll
        for (int b = 0; b < 4; b++)
#pragma unroll
            for (int c = 0; c < 4; c++) acc[a][b][c] = 0.0f;

    auto load_tiles = [&](int it, float* As, float* Bs) {
#pragma unroll
        for (int i = 0; i < CA; i++) {
            int f = tid + TPB * i;
            int m = f >> 3, q = f & 7;
            int gr = block_m + m;
            uint32_t dst = (uint32_t)__cvta_generic_to_shared(As + m * AST + 4 * q);
            const float* src = A + (size_t)gr * K + it * BK + 4 * q;
            int sz = (gr < M) ? 16 : 0;
            asm volatile("cp.async.cg.shared.global [%0], [%1], 16, %2;"
                         :: "r"(dst), "l"(src), "r"(sz));
        }
#pragma unroll
        for (int i = 0; i < CB; i++) {
            int f = tid + TPB * i;
            int n4 = f % (BN / 4), k = f / (BN / 4);
            uint32_t dst = (uint32_t)__cvta_generic_to_shared(Bs + k * BST + 4 * n4);
            const float* src = B + (size_t)(it * BK + k) * N + block_n + 4 * n4;
            asm volatile("cp.async.cg.shared.global [%0], [%1], 16;"
                         :: "r"(dst), "l"(src));
        }
        asm volatile("cp.async.commit_group;");
    };

    int nIter = K / BK;
    load_tiles(0, AsB, BsB);

    for (int it = 0; it < nIter; ++it) {
        int buf = it & 1;
        if (it + 1 < nIter) {
            load_tiles(it + 1, AsB + (buf ^ 1) * ATILE, BsB + (buf ^ 1) * BTILE);
            asm volatile("cp.async.wait_group 1;");
        } else {
            asm volatile("cp.async.wait_group 0;");
        }
        __syncthreads();
        const float* As = AsB + buf * ATILE;
        const float* Bs = BsB + buf * BTILE;

#pragma unroll
        for (int ks = 0; ks < 4; ks++) {
            int col = ks * 8 + lc;
            uint32_t af[4][4], bfr[4][2];
#pragma unroll
            for (int mt = 0; mt < 4; mt++) {
                const float* ap = As + (wm * 64 + mt * 16 + lr) * AST + col;
                if (CVTA) {
                    af[mt][0] = tf32u(ap[0]);
                    af[mt][1] = tf32u(ap[8 * AST]);
                    af[mt][2] = tf32u(ap[4]);
                    af[mt][3] = tf32u(ap[8 * AST + 4]);
                } else {
                    af[mt][0] = __float_as_uint(ap[0]);
                    af[mt][1] = __float_as_uint(ap[8 * AST]);
                    af[mt][2] = __float_as_uint(ap[4]);
                    af[mt][3] = __float_as_uint(ap[8 * AST + 4]);
                }
            }
#pragma unroll
            for (int nt = 0; nt < 4; nt++) {
                const float* bp = Bs + col * BST + wn * 32 + nt * 8 + lr;
                bfr[nt][0] = __float_as_uint(bp[0]);
                bfr[nt][1] = __float_as_uint(bp[4 * BST]);
            }
#pragma unroll
            for (int mt = 0; mt < 4; mt++)
#pragma unroll
                for (int nt = 0; nt < 4; nt++)
                    asm volatile(
                        "mma.sync.aligned.m16n8k8.row.col.f32.tf32.tf32.f32 "
                        "{%0,%1,%2,%3}, {%4,%5,%6,%7}, {%8,%9}, {%0,%1,%2,%3};"
                        : "+f"(acc[mt][nt][0]), "+f"(acc[mt][nt][1]),
                          "+f"(acc[mt][nt][2]), "+f"(acc[mt][nt][3])
                        : "r"(af[mt][0]), "r"(af[mt][1]), "r"(af[mt][2]), "r"(af[mt][3]),
                          "r"(bfr[nt][0]), "r"(bfr[nt][1]));
        }
        __syncthreads();
    }

    // epilogue
#pragma unroll
    for (int mt = 0; mt < 4; mt++) {
#pragma unroll
        for (int half = 0; half < 2; half++) {
            int row = block_m + wm * 64 + mt * 16 + lr + half * 8;
            if (row >= M) continue;
            float rs = rowscale ? rowscale[row] : 1.0f;
#pragma unroll
            for (int nt = 0; nt < 4; nt++) {
                int gc = block_n + wn * 32 + nt * 8 + 2 * lc;
                float v0 = acc[mt][nt][half * 2 + 0];
                float v1 = acc[mt][nt][half * 2 + 1];
                if (D) {
                    float2 d = *(const float2*)(D + (size_t)row * N + gc);
                    v0 += d.x; v1 += d.y;
                }
                float b0 = 0.0f, b1 = 0.0f;
                if (bias) { b0 = bias[gc]; b1 = bias[gc + 1]; }
                v0 = rs * v0 + b0;
                v1 = rs * v1 + b1;
                if (RELU) { v0 = fmaxf(v0, 0.0f); v1 = fmaxf(v1, 0.0f); }
                if (ROUND) { v0 = tf32r(v0); v1 = tf32r(v1); }
                *(float2*)(C + (size_t)row * N + gc) = make_float2(v0, v1);
            }
        }
    }
}

constexpr size_t smem_bytes(int WMW, int WNW) {
    return (size_t)(2 * (WMW * 64) * 36 + 2 * 32 * (WNW * 32 + 8)) * 4;
}

// ---------------- edge kernel -----------------------------------------------
__device__ __forceinline__ void red4(float* p, float4 v) {
    asm volatile("red.global.add.v4.f32 [%0], {%1,%2,%3,%4};"
                 :: "l"(p), "f"(v.x), "f"(v.y), "f"(v.z), "f"(v.w) : "memory");
}

__global__ __launch_bounds__(256) void edge_kernel(const int* __restrict__ en) {
    int wg = (blockIdx.x * blockDim.x + threadIdx.x) >> 5;
    int lane = threadIdx.x & 31;
    if (wg >= NEDGE) return;
    int v0 = en[wg * 3 + 0];
    int v1 = en[wg * 3 + 1];
    int v2 = en[wg * 3 + 2];
    float d0 = g_dscale[v0], d1 = g_dscale[v1], d2 = g_dscale[v2];

    if (lane < 16) {
        float4 a = *(const float4*)(g_emb_new + (size_t)v0 * RANK + lane * 4);
        float4 b = *(const float4*)(g_emb_new + (size_t)v1 * RANK + lane * 4);
        float4 c = *(const float4*)(g_emb_new + (size_t)v2 * RANK + lane * 4);
        a.x *= d0; a.y *= d0; a.z *= d0; a.w *= d0;
        b.x *= d1; b.y *= d1; b.z *= d1; b.w *= d1;
        c.x *= d2; c.y *= d2; c.z *= d2; c.w *= d2;
        float h0 = 0.5f * d0, h1 = 0.5f * d1, h2 = 0.5f * d2;
        float4 o0 = make_float4(h0 * b.x * c.x, h0 * b.y * c.y, h0 * b.z * c.z, h0 * b.w * c.w);
        float4 o1 = make_float4(h1 * a.x * c.x, h1 * a.y * c.y, h1 * a.z * c.z, h1 * a.w * c.w);
        float4 o2 = make_float4(h2 * a.x * b.x, h2 * a.y * b.y, h2 * a.z * b.z, h2 * a.w * b.w);
        red4(g_sum_c1 + (size_t)v0 * RANK + lane * 4, o0);
        red4(g_sum_c1 + (size_t)v1 * RANK + lane * 4, o1);
        red4(g_sum_c1 + (size_t)v2 * RANK + lane * 4, o2);
    }

    const float4* e0 = (const float4*)(g_emb2) + (size_t)v0 * (OUTD / 4);
    const float4* e1 = (const float4*)(g_emb2) + (size_t)v1 * (OUTD / 4);
    const float4* e2p = (const float4*)(g_emb2) + (size_t)v2 * (OUTD / 4);
#pragma unroll
    for (int t = 0; t < 2; t++) {
        int c4 = lane + t * 32;
        float4 x = e0[c4], y = e1[c4], z = e2p[c4];
        float4 s = make_float4(fmaxf(x.x + y.x + z.x, 0.0f),
                               fmaxf(x.y + y.y + z.y, 0.0f),
                               fmaxf(x.z + y.z + z.z, 0.0f),
                               fmaxf(x.w + y.w + z.w, 0.0f));
        red4(g_sum_s + (size_t)v0 * OUTD + c4 * 4, s);
        red4(g_sum_s + (size_t)v1 * OUTD + c4 * 4, s);
        red4(g_sum_s + (size_t)v2 * OUTD + c4 * 4, s);
    }
}

// ---------------- launch ----------------------------------------------------
extern "C" void kernel_launch(void* const* d_in, const int* in_sizes, int n_in,
                              void* d_out, int out_size) {
    const float* emb = (const float*)d_in[0];
    const int*   en  = (const int*)d_in[1];
    const float* Wp  = (const float*)d_in[2];
    const float* bp  = (const float*)d_in[3];
    const float* W2a = (const float*)d_in[4];
    const float* b2a = (const float*)d_in[5];
    const float* W2b = (const float*)d_in[6];
    const float* b2b = (const float*)d_in[7];
    const float* Wq  = (const float*)d_in[8];
    const float* bq  = (const float*)d_in[9];
    float* out = (float*)d_out;

    float *p_emb_new, *p_hid, *p_emb2, *p_sum_c1, *p_sum_s, *p_invdeg;
    float *p_emb_r, *p_wp_r, *p_w2a_r, *p_w2b_r, *p_wq_r, *p_bias1, *p_bias2;
    cudaGetSymbolAddress((void**)&p_emb_new, g_emb_new);
    cudaGetSymbolAddress((void**)&p_hid,     g_hid);
    cudaGetSymbolAddress((void**)&p_emb2,    g_emb2);
    cudaGetSymbolAddress((void**)&p_sum_c1,  g_sum_c1);
    cudaGetSymbolAddress((void**)&p_sum_s,   g_sum_s);
    cudaGetSymbolAddress((void**)&p_invdeg,  g_invdeg);
    cudaGetSymbolAddress((void**)&p_emb_r,   g_emb_r);
    cudaGetSymbolAddress((void**)&p_wp_r,    g_wp_r);
    cudaGetSymbolAddress((void**)&p_w2a_r,   g_w2a_r);
    cudaGetSymbolAddress((void**)&p_w2b_r,   g_w2b_r);
    cudaGetSymbolAddress((void**)&p_wq_r,    g_wq_r);
    cudaGetSymbolAddress((void**)&p_bias1,   g_bias1);
    cudaGetSymbolAddress((void**)&p_bias2,   g_bias2);

    constexpr size_t SM42  = smem_bytes(4, 2);   // 92160  (G1: 256x64, 256 thr)
    constexpr size_t SM28  = smem_bytes(2, 8);   // 104448 (G2/3/4: 128x256, 512 thr)
    cudaFuncSetAttribute(gemm_v2<4,2,256,false,false,false>, cudaFuncAttributeMaxDynamicSharedMemorySize, (int)SM42);
    cudaFuncSetAttribute(gemm_v2<2,8,512,true, true, false>, cudaFuncAttributeMaxDynamicSharedMemorySize, (int)SM28);
    cudaFuncSetAttribute(gemm_v2<2,8,512,false,false,false>, cudaFuncAttributeMaxDynamicSharedMemorySize, (int)SM28);
    cudaFuncSetAttribute(gemm_v2<2,8,512,true, false,true >, cudaFuncAttributeMaxDynamicSharedMemorySize, (int)SM28);

    const int M = N_NODES;

    // Launch order puts G2 at position 4 (the slot ncu profiles).
    {
        int total = FEAT * RANK + FEAT * HIDD + HIDD * OUTD + RANK * OUTD + RANK + HIDD;
        wprep_kernel<<<(total + 255) / 256, 256>>>(Wp, bp, W2a, b2a, W2b, Wq);  // 1
    }
    {
        int n4 = N_NODES * FEAT / 4;
        round_tf32_kernel<<<(n4 + 255) / 256, 256>>>((const float4*)emb, (float4*)p_emb_r, n4); // 2
    }
    zero_kernel<<<1024, 256>>>();                                   // 3

    // 4: G2: hid = round(relu(emb @ W2a + bias2))   [128x256, 512 thr]
    gemm_v2<2,8,512,true,true,false><<<dim3(HIDD / 256, (M + 127) / 128), 512, SM28>>>(
        M, HIDD, FEAT, p_emb_r, p_w2a_r, p_bias2, nullptr, nullptr, p_hid);
    // 5: G1: emb_new = emb @ Wp + bias1             [256x64, 256 thr]
    gemm_v2<4,2,256,false,false,false><<<dim3(1, (M + 255) / 256), 256, SM42>>>(
        M, RANK, FEAT, p_emb_r, p_wp_r, p_bias1, nullptr, nullptr, p_emb_new);
    // 6: G3: emb2 = hid @ W2b + b2b                 [128x256, 512 thr]
    gemm_v2<2,8,512,false,false,false><<<dim3(1, (M + 127) / 128), 512, SM28>>>(
        M, OUTD, HIDD, p_hid, p_w2b_r, b2b, nullptr, nullptr, p_emb2);
    // 7,8: degree prep (needed by edge + G4 only)
    deg_kernel<<<(NEDGE * KE + 255) / 256, 256>>>(en);
    scale_kernel<<<(N_NODES + 255) / 256, 256>>>();
    // 9: edge scatter
    edge_kernel<<<(NEDGE * 32) / 256, 256>>>(en);
    // 10: G4: out = relu(invdeg * (sum_c1 @ Wq + sum_s) + bq)  [CVTA]
    gemm_v2<2,8,512,true,false,true><<<dim3(1, (M + 127) / 128), 512, SM28>>>(
        M, OUTD, RANK, p_sum_c1, p_wq_r, bq, p_sum_s, p_invdeg, out);
}

// round 11
// speedup vs baseline: 1.2470x; 1.1547x over previous
#include <cuda_runtime.h>
#include <math.h>
#include <stdint.h>

#define N_NODES 100000
#define FEAT    256
#define RANK    64
#define HIDD    512
#define OUTD    256
#define NEDGE   200000
#define KE      3
#define CSRCAP  12

// ---------------- scratch (device globals; no allocations allowed) ----------
__device__ __align__(16) float g_emb_new[N_NODES * RANK];
__device__ __align__(16) float g_hid[N_NODES * HIDD];
__device__ __align__(16) float g_emb2[N_NODES * OUTD];
__device__ __align__(16) float g_sum_c1[N_NODES * RANK];
__device__ __align__(16) float g_sum_s[N_NODES * OUTD];
__device__ __align__(16) float g_relu_s[(size_t)NEDGE * OUTD];   // 204.8 MB
__device__ __align__(16) float g_emb_r[N_NODES * FEAT];
__device__ __align__(16) float g_wp_r[FEAT * RANK];
__device__ __align__(16) float g_w2a_r[FEAT * HIDD];
__device__ __align__(16) float g_w2b_r[HIDD * OUTD];
__device__ __align__(16) float g_wq_r[RANK * OUTD];
__device__ __align__(16) float g_bias1[RANK];
__device__ __align__(16) float g_bias2[HIDD];
__device__ int   g_csr[N_NODES * CSRCAP];
__device__ int   g_deg[N_NODES];
__device__ float g_dscale[N_NODES];
__device__ float g_invdeg[N_NODES];

__device__ __forceinline__ float tf32r(float x) {
    uint32_t r;
    asm("cvt.rna.tf32.f32 %0, %1;" : "=r"(r) : "f"(x));
    return __uint_as_float(r);
}
__device__ __forceinline__ uint32_t tf32u(float x) {
    uint32_t r;
    asm("cvt.rna.tf32.f32 %0, %1;" : "=r"(r) : "f"(x));
    return r;
}

// ---------------- utility kernels -------------------------------------------
__global__ void zero_kernel() {
    int i = blockIdx.x * blockDim.x + threadIdx.x;
    int stride = gridDim.x * blockDim.x;
    float4 z = make_float4(0.f, 0.f, 0.f, 0.f);
    float4* c4 = (float4*)g_sum_c1;
    for (int t = i; t < N_NODES * RANK / 4; t += stride) c4[t] = z;
    for (int t = i; t < N_NODES; t += stride) g_deg[t] = 0;
}

// build CSR (node -> incident edge list) + degree counts
__global__ void csr_kernel(const int* __restrict__ en) {
    int i = blockIdx.x * blockDim.x + threadIdx.x;
    if (i < NEDGE * KE) {
        int v = en[i];
        int pos = atomicAdd(&g_deg[v], 1);
        if (pos < CSRCAP) g_csr[v * CSRCAP + pos] = i / KE;   // edge id
    }
}

__global__ void scale_kernel() {
    int v = blockIdx.x * blockDim.x + threadIdx.x;
    if (v < N_NODES) {
        float d = (float)g_deg[v];
        g_dscale[v] = cbrtf(d);
        g_invdeg[v] = 1.0f / d;
    }
}

__global__ void round_tf32_kernel(const float4* __restrict__ src,
                                  float4* __restrict__ dst, int n4) {
    int i = blockIdx.x * blockDim.x + threadIdx.x;
    if (i < n4) {
        float4 v = src[i];
        v.x = tf32r(v.x); v.y = tf32r(v.y); v.z = tf32r(v.z); v.w = tf32r(v.w);
        dst[i] = v;
    }
}

__global__ void wprep_kernel(const float* __restrict__ Wp,  const float* __restrict__ bp,
                             const float* __restrict__ W2a, const float* __restrict__ b2a,
                             const float* __restrict__ W2b,
                             const float* __restrict__ Wq) {
    const int S1 = FEAT * RANK;
    const int S2 = S1 + FEAT * HIDD;
    const int S3 = S2 + HIDD * OUTD;
    const int S4 = S3 + RANK * OUTD;
    const int S5 = S4 + RANK;
    const int S6 = S5 + HIDD;
    int i = blockIdx.x * blockDim.x + threadIdx.x;
    if (i < S1) g_wp_r[i] = tf32r(Wp[i]);
    else if (i < S2) { int j = i - S1; g_w2a_r[j] = tf32r(W2a[j]); }
    else if (i < S3) { int j = i - S2; g_w2b_r[j] = tf32r(W2b[j]); }
    else if (i < S4) { int j = i - S3; g_wq_r[j]  = tf32r(Wq[j]); }
    else if (i < S5) { int j = i - S4; g_bias1[j] = Wp[FEAT * RANK + j] + bp[j]; }
    else if (i < S6) { int j = i - S5; g_bias2[j] = W2a[FEAT * HIDD + j] + b2a[j]; }
}

// ---------------- TF32 tensor-core GEMM (round-8 structure) ------------------
template <int WMW, int WNW, int TPB, bool RELU, bool ROUND, bool CVTA>
__global__ __launch_bounds__(TPB) void gemm_v2(
    int M, int N, int K,
    const float* __restrict__ A, const float* __restrict__ B,
    const float* __restrict__ bias,
    const float* __restrict__ D, const float* __restrict__ rowscale,
    float* __restrict__ C)
{
    constexpr int BM = WMW * 64, BN = WNW * 32, BK = 32;
    constexpr int AST = BK + 4;
    constexpr int BST = BN + 8;
    constexpr int ATILE = BM * AST;
    constexpr int BTILE = BK * BST;
    constexpr int CA = BM * BK / (4 * TPB);
    constexpr int CB = BK * BN / (4 * TPB);
    static_assert(CA >= 1 && CB >= 1, "tile/thread mismatch");
    static_assert(WMW * WNW * 32 == TPB, "warp layout mismatch");

    extern __shared__ float smem[];
    float* AsB = smem;
    float* BsB = smem + 2 * ATILE;

    int tid = threadIdx.x;
    int warp = tid >> 5, lane = tid & 31;
    int wm = warp / WNW, wn = warp % WNW;
    int lr = lane >> 2, lc = lane & 3;
    int block_m = blockIdx.y * BM, block_n = blockIdx.x * BN;

    float acc[4][4][4];
#pragma unroll
    for (int a = 0; a < 4; a++)
#pragma unroll
        for (int b = 0; b < 4; b++)
#pragma unroll
            for (int c = 0; c < 4; c++) acc[a][b][c] = 0.0f;

    auto load_tiles = [&](int it, float* As, float* Bs) {
#pragma unroll
        for (int i = 0; i < CA; i++) {
            int f = tid + TPB * i;
            int m = f >> 3, q = f & 7;
            int gr = block_m + m;
            uint32_t dst = (uint32_t)__cvta_generic_to_shared(As + m * AST + 4 * q);
            const float* src = A + (size_t)gr * K + it * BK + 4 * q;
            int sz = (gr < M) ? 16 : 0;
            asm volatile("cp.async.cg.shared.global [%0], [%1], 16, %2;"
                         :: "r"(dst), "l"(src), "r"(sz));
        }
#pragma unroll
        for (int i = 0; i < CB; i++) {
            int f = tid + TPB * i;
            int n4 = f % (BN / 4), k = f / (BN / 4);
            uint32_t dst = (uint32_t)__cvta_generic_to_shared(Bs + k * BST + 4 * n4);
            const float* src = B + (size_t)(it * BK + k) * N + block_n + 4 * n4;
            asm volatile("cp.async.cg.shared.global [%0], [%1], 16;"
                         :: "r"(dst), "l"(src));
        }
        asm volatile("cp.async.commit_group;");
    };

    int nIter = K / BK;
    load_tiles(0, AsB, BsB);

    for (int it = 0; it < nIter; ++it) {
        int buf = it & 1;
        if (it + 1 < nIter) {
            load_tiles(it + 1, AsB + (buf ^ 1) * ATILE, BsB + (buf ^ 1) * BTILE);
            asm volatile("cp.async.wait_group 1;");
        } else {
            asm volatile("cp.async.wait_group 0;");
        }
        __syncthreads();
        const float* As = AsB + buf * ATILE;
        const float* Bs = BsB + buf * BTILE;

#pragma unroll
        for (int ks = 0; ks < 4; ks++) {
            int col = ks * 8 + lc;
            uint32_t af[4][4], bfr[4][2];
#pragma unroll
            for (int mt = 0; mt < 4; mt++) {
                const float* ap = As + (wm * 64 + mt * 16 + lr) * AST + col;
                if (CVTA) {
                    af[mt][0] = tf32u(ap[0]);
                    af[mt][1] = tf32u(ap[8 * AST]);
                    af[mt][2] = tf32u(ap[4]);
                    af[mt][3] = tf32u(ap[8 * AST + 4]);
                } else {
                    af[mt][0] = __float_as_uint(ap[0]);
                    af[mt][1] = __float_as_uint(ap[8 * AST]);
                    af[mt][2] = __float_as_uint(ap[4]);
                    af[mt][3] = __float_as_uint(ap[8 * AST + 4]);
                }
            }
#pragma unroll
            for (int nt = 0; nt < 4; nt++) {
                const float* bp = Bs + col * BST + wn * 32 + nt * 8 + lr;
                bfr[nt][0] = __float_as_uint(bp[0]);
                bfr[nt][1] = __float_as_uint(bp[4 * BST]);
            }
#pragma unroll
            for (int mt = 0; mt < 4; mt++)
#pragma unroll
                for (int nt = 0; nt < 4; nt++)
                    asm volatile(
                        "mma.sync.aligned.m16n8k8.row.col.f32.tf32.tf32.f32 "
                        "{%0,%1,%2,%3}, {%4,%5,%6,%7}, {%8,%9}, {%0,%1,%2,%3};"
                        : "+f"(acc[mt][nt][0]), "+f"(acc[mt][nt][1]),
                          "+f"(acc[mt][nt][2]), "+f"(acc[mt][nt][3])
                        : "r"(af[mt][0]), "r"(af[mt][1]), "r"(af[mt][2]), "r"(af[mt][3]),
                          "r"(bfr[nt][0]), "r"(bfr[nt][1]));
        }
        __syncthreads();
    }

    // epilogue
#pragma unroll
    for (int mt = 0; mt < 4; mt++) {
#pragma unroll
        for (int half = 0; half < 2; half++) {
            int row = block_m + wm * 64 + mt * 16 + lr + half * 8;
            if (row >= M) continue;
            float rs = rowscale ? rowscale[row] : 1.0f;
#pragma unroll
            for (int nt = 0; nt < 4; nt++) {
                int gc = block_n + wn * 32 + nt * 8 + 2 * lc;
                float v0 = acc[mt][nt][half * 2 + 0];
                float v1 = acc[mt][nt][half * 2 + 1];
                if (D) {
                    float2 d = *(const float2*)(D + (size_t)row * N + gc);
                    v0 += d.x; v1 += d.y;
                }
                float b0 = 0.0f, b1 = 0.0f;
                if (bias) { b0 = bias[gc]; b1 = bias[gc + 1]; }
                v0 = rs * v0 + b0;
                v1 = rs * v1 + b1;
                if (RELU) { v0 = fmaxf(v0, 0.0f); v1 = fmaxf(v1, 0.0f); }
                if (ROUND) { v0 = tf32r(v0); v1 = tf32r(v1); }
                *(float2*)(C + (size_t)row * N + gc) = make_float2(v0, v1);
            }
        }
    }
}

constexpr size_t smem_bytes(int WMW, int WNW) {
    return (size_t)(2 * (WMW * 64) * 36 + 2 * 32 * (WNW * 32 + 8)) * 4;
}

// ---------------- edge kernel (c1 atomics + relu_s plain store) --------------
__device__ __forceinline__ void red4(float* p, float4 v) {
    asm volatile("red.global.add.v4.f32 [%0], {%1,%2,%3,%4};"
                 :: "l"(p), "f"(v.x), "f"(v.y), "f"(v.z), "f"(v.w) : "memory");
}

__global__ __launch_bounds__(256) void edge_kernel(const int* __restrict__ en) {
    int wg = (blockIdx.x * blockDim.x + threadIdx.x) >> 5;
    int lane = threadIdx.x & 31;
    if (wg >= NEDGE) return;
    int v0 = en[wg * 3 + 0];
    int v1 = en[wg * 3 + 1];
    int v2 = en[wg * 3 + 2];
    float d0 = g_dscale[v0], d1 = g_dscale[v1], d2 = g_dscale[v2];

    if (lane < 16) {
        float4 a = *(const float4*)(g_emb_new + (size_t)v0 * RANK + lane * 4);
        float4 b = *(const float4*)(g_emb_new + (size_t)v1 * RANK + lane * 4);
        float4 c = *(const float4*)(g_emb_new + (size_t)v2 * RANK + lane * 4);
        a.x *= d0; a.y *= d0; a.z *= d0; a.w *= d0;
        b.x *= d1; b.y *= d1; b.z *= d1; b.w *= d1;
        c.x *= d2; c.y *= d2; c.z *= d2; c.w *= d2;
        float h0 = 0.5f * d0, h1 = 0.5f * d1, h2 = 0.5f * d2;
        float4 o0 = make_float4(h0 * b.x * c.x, h0 * b.y * c.y, h0 * b.z * c.z, h0 * b.w * c.w);
        float4 o1 = make_float4(h1 * a.x * c.x, h1 * a.y * c.y, h1 * a.z * c.z, h1 * a.w * c.w);
        float4 o2 = make_float4(h2 * a.x * b.x, h2 * a.y * b.y, h2 * a.z * b.z, h2 * a.w * b.w);
        red4(g_sum_c1 + (size_t)v0 * RANK + lane * 4, o0);
        red4(g_sum_c1 + (size_t)v1 * RANK + lane * 4, o1);
        red4(g_sum_c1 + (size_t)v2 * RANK + lane * 4, o2);
    }

    const float4* e0 = (const float4*)(g_emb2) + (size_t)v0 * (OUTD / 4);
    const float4* e1 = (const float4*)(g_emb2) + (size_t)v1 * (OUTD / 4);
    const float4* e2p = (const float4*)(g_emb2) + (size_t)v2 * (OUTD / 4);
    float4* rout = (float4*)(g_relu_s + (size_t)wg * OUTD);
#pragma unroll
    for (int t = 0; t < 2; t++) {
        int c4 = lane + t * 32;
        float4 x = e0[c4], y = e1[c4], z = e2p[c4];
        float4 s = make_float4(fmaxf(x.x + y.x + z.x, 0.0f),
                               fmaxf(x.y + y.y + z.y, 0.0f),
                               fmaxf(x.z + y.z + z.z, 0.0f),
                               fmaxf(x.w + y.w + z.w, 0.0f));
        rout[c4] = s;                               // single coalesced store
    }
}

// ---------------- node gather: sum_s[v] = sum over incident edges ------------
__global__ __launch_bounds__(256) void gather_kernel() {
    int v = (blockIdx.x * blockDim.x + threadIdx.x) >> 5;
    int lane = threadIdx.x & 31;
    if (v >= N_NODES) return;
    int d = g_deg[v];
    if (d > CSRCAP) d = CSRCAP;
    float4 a0 = make_float4(0.f, 0.f, 0.f, 0.f);
    float4 a1 = a0;
    for (int t = 0; t < d; t++) {
        int e = g_csr[v * CSRCAP + t];
        const float4* r = (const float4*)(g_relu_s + (size_t)e * OUTD);
        float4 x0 = r[lane * 2], x1 = r[lane * 2 + 1];
        a0.x += x0.x; a0.y += x0.y; a0.z += x0.z; a0.w += x0.w;
        a1.x += x1.x; a1.y += x1.y; a1.z += x1.z; a1.w += x1.w;
    }
    float4* o = (float4*)(g_sum_s + (size_t)v * OUTD);
    o[lane * 2] = a0;
    o[lane * 2 + 1] = a1;
}

// ---------------- launch ----------------------------------------------------
extern "C" void kernel_launch(void* const* d_in, const int* in_sizes, int n_in,
                              void* d_out, int out_size) {
    const float* emb = (const float*)d_in[0];
    const int*   en  = (const int*)d_in[1];
    const float* Wp  = (const float*)d_in[2];
    const float* bp  = (const float*)d_in[3];
    const float* W2a = (const float*)d_in[4];
    const float* b2a = (const float*)d_in[5];
    const float* W2b = (const float*)d_in[6];
    const float* b2b = (const float*)d_in[7];
    const float* Wq  = (const float*)d_in[8];
    const float* bq  = (const float*)d_in[9];
    float* out = (float*)d_out;

    float *p_emb_new, *p_hid, *p_emb2, *p_sum_c1, *p_sum_s, *p_invdeg;
    float *p_emb_r, *p_wp_r, *p_w2a_r, *p_w2b_r, *p_wq_r, *p_bias1, *p_bias2;
    cudaGetSymbolAddress((void**)&p_emb_new, g_emb_new);
    cudaGetSymbolAddress((void**)&p_hid,     g_hid);
    cudaGetSymbolAddress((void**)&p_emb2,    g_emb2);
    cudaGetSymbolAddress((void**)&p_sum_c1,  g_sum_c1);
    cudaGetSymbolAddress((void**)&p_sum_s,   g_sum_s);
    cudaGetSymbolAddress((void**)&p_invdeg,  g_invdeg);
    cudaGetSymbolAddress((void**)&p_emb_r,   g_emb_r);
    cudaGetSymbolAddress((void**)&p_wp_r,    g_wp_r);
    cudaGetSymbolAddress((void**)&p_w2a_r,   g_w2a_r);
    cudaGetSymbolAddress((void**)&p_w2b_r,   g_w2b_r);
    cudaGetSymbolAddress((void**)&p_wq_r,    g_wq_r);
    cudaGetSymbolAddress((void**)&p_bias1,   g_bias1);
    cudaGetSymbolAddress((void**)&p_bias2,   g_bias2);

    constexpr size_t SM42 = smem_bytes(4, 2);   // 92160  (G1)
    constexpr size_t SM18 = smem_bytes(1, 8);   // 86016  (G2/G3/G4)
    cudaFuncSetAttribute(gemm_v2<4,2,256,false,false,false>, cudaFuncAttributeMaxDynamicSharedMemorySize, (int)SM42);
    cudaFuncSetAttribute(gemm_v2<1,8,256,true, true, false>, cudaFuncAttributeMaxDynamicSharedMemorySize, (int)SM18);
    cudaFuncSetAttribute(gemm_v2<1,8,256,false,false,false>, cudaFuncAttributeMaxDynamicSharedMemorySize, (int)SM18);
    cudaFuncSetAttribute(gemm_v2<1,8,256,true, false,true >, cudaFuncAttributeMaxDynamicSharedMemorySize, (int)SM18);

    const int M = N_NODES;

    // 1..3: prep  (slot 4 = G2 for the ncu window)
    {
        int total = FEAT * RANK + FEAT * HIDD + HIDD * OUTD + RANK * OUTD + RANK + HIDD;
        wprep_kernel<<<(total + 255) / 256, 256>>>(Wp, bp, W2a, b2a, W2b, Wq);  // 1
    }
    {
        int n4 = N_NODES * FEAT / 4;
        round_tf32_kernel<<<(n4 + 255) / 256, 256>>>((const float4*)emb, (float4*)p_emb_r, n4); // 2
    }
    zero_kernel<<<1024, 256>>>();                                   // 3

    // 4: G2: hid = round(relu(emb @ W2a + bias2))   [64x256, 256 thr]
    gemm_v2<1,8,256,true,true,false><<<dim3(HIDD / 256, (M + 63) / 64), 256, SM18>>>(
        M, HIDD, FEAT, p_emb_r, p_w2a_r, p_bias2, nullptr, nullptr, p_hid);
    // 5: G1: emb_new = emb @ Wp + bias1             [256x64, 256 thr]
    gemm_v2<4,2,256,false,false,false><<<dim3(1, (M + 255) / 256), 256, SM42>>>(
        M, RANK, FEAT, p_emb_r, p_wp_r, p_bias1, nullptr, nullptr, p_emb_new);
    // 6: G3: emb2 = hid @ W2b + b2b                 [64x256, 256 thr]
    gemm_v2<1,8,256,false,false,false><<<dim3(1, (M + 63) / 64), 256, SM18>>>(
        M, OUTD, HIDD, p_hid, p_w2b_r, b2b, nullptr, nullptr, p_emb2);
    // 7: CSR build (+degree)
    csr_kernel<<<(NEDGE * KE + 255) / 256, 256>>>(en);
    // 8: degree-derived scales
    scale_kernel<<<(N_NODES + 255) / 256, 256>>>();
    // 9: edge kernel: c1 atomics + relu_s store
    edge_kernel<<<(NEDGE * 32) / 256, 256>>>(en);
    // 10: node gather: sum_s
    gather_kernel<<<(N_NODES * 32 + 255) / 256, 256>>>();
    // 11: G4: out = relu(invdeg * (sum_c1 @ Wq + sum_s) + bq)  [CVTA]
    gemm_v2<1,8,256,true,false,true><<<dim3(1, (M + 63) / 64), 256, SM18>>>(
        M, OUTD, RANK, p_sum_c1, p_wq_r, bq, p_sum_s, p_invdeg, out);
}

// round 12
// speedup vs baseline: 1.3497x; 1.0823x over previous
#include <cuda_runtime.h>
#include <cuda_fp16.h>
#include <math.h>
#include <stdint.h>

#define N_NODES 100000
#define FEAT    256
#define RANK    64
#define HIDD    512
#define OUTD    256
#define NEDGE   200000
#define KE      3
#define CSRCAP  12

// ---------------- scratch (device globals; no allocations allowed) ----------
__device__ __align__(16) float g_emb_new[N_NODES * RANK];
__device__ __align__(16) float g_hid[N_NODES * HIDD];
__device__ __align__(16) float g_emb2[N_NODES * OUTD];
__device__ __align__(16) float g_sum_c1[N_NODES * RANK];
__device__ __align__(16) float g_sum_s[N_NODES * OUTD];
__device__ __align__(16) __half g_relu_s[(size_t)NEDGE * OUTD];  // 102.4 MB (fp16)
__device__ __align__(16) float g_emb_r[N_NODES * FEAT];
__device__ __align__(16) float g_wp_r[FEAT * RANK];
__device__ __align__(16) float g_w2a_r[FEAT * HIDD];
__device__ __align__(16) float g_w2b_r[HIDD * OUTD];
__device__ __align__(16) float g_wq_r[RANK * OUTD];
__device__ __align__(16) float g_bias1[RANK];
__device__ __align__(16) float g_bias2[HIDD];
__device__ int   g_csr[N_NODES * CSRCAP];
__device__ int   g_deg[N_NODES];
__device__ float g_dscale[N_NODES];
__device__ float g_invdeg[N_NODES];

__device__ __forceinline__ float tf32r(float x) {
    uint32_t r;
    asm("cvt.rna.tf32.f32 %0, %1;" : "=r"(r) : "f"(x));
    return __uint_as_float(r);
}
__device__ __forceinline__ uint32_t tf32u(float x) {
    uint32_t r;
    asm("cvt.rna.tf32.f32 %0, %1;" : "=r"(r) : "f"(x));
    return r;
}

// ---------------- utility kernels -------------------------------------------
__global__ void zero_kernel() {
    int i = blockIdx.x * blockDim.x + threadIdx.x;
    int stride = gridDim.x * blockDim.x;
    float4 z = make_float4(0.f, 0.f, 0.f, 0.f);
    float4* c4 = (float4*)g_sum_c1;
    for (int t = i; t < N_NODES * RANK / 4; t += stride) c4[t] = z;
    for (int t = i; t < N_NODES; t += stride) g_deg[t] = 0;
}

__global__ void csr_kernel(const int* __restrict__ en) {
    int i = blockIdx.x * blockDim.x + threadIdx.x;
    if (i < NEDGE * KE) {
        int v = en[i];
        int pos = atomicAdd(&g_deg[v], 1);
        if (pos < CSRCAP) g_csr[v * CSRCAP + pos] = i / KE;
    }
}

__global__ void scale_kernel() {
    int v = blockIdx.x * blockDim.x + threadIdx.x;
    if (v < N_NODES) {
        float d = (float)g_deg[v];
        g_dscale[v] = cbrtf(d);
        g_invdeg[v] = 1.0f / d;
    }
}

__global__ void round_tf32_kernel(const float4* __restrict__ src,
                                  float4* __restrict__ dst, int n4) {
    int i = blockIdx.x * blockDim.x + threadIdx.x;
    if (i < n4) {
        float4 v = src[i];
        v.x = tf32r(v.x); v.y = tf32r(v.y); v.z = tf32r(v.z); v.w = tf32r(v.w);
        dst[i] = v;
    }
}

__global__ void wprep_kernel(const float* __restrict__ Wp,  const float* __restrict__ bp,
                             const float* __restrict__ W2a, const float* __restrict__ b2a,
                             const float* __restrict__ W2b,
                             const float* __restrict__ Wq) {
    const int S1 = FEAT * RANK;
    const int S2 = S1 + FEAT * HIDD;
    const int S3 = S2 + HIDD * OUTD;
    const int S4 = S3 + RANK * OUTD;
    const int S5 = S4 + RANK;
    const int S6 = S5 + HIDD;
    int i = blockIdx.x * blockDim.x + threadIdx.x;
    if (i < S1) g_wp_r[i] = tf32r(Wp[i]);
    else if (i < S2) { int j = i - S1; g_w2a_r[j] = tf32r(W2a[j]); }
    else if (i < S3) { int j = i - S2; g_w2b_r[j] = tf32r(W2b[j]); }
    else if (i < S4) { int j = i - S3; g_wq_r[j]  = tf32r(Wq[j]); }
    else if (i < S5) { int j = i - S4; g_bias1[j] = Wp[FEAT * RANK + j] + bp[j]; }
    else if (i < S6) { int j = i - S5; g_bias2[j] = W2a[FEAT * HIDD + j] + b2a[j]; }
}

// ---------------- TF32 tensor-core GEMM (round-8 structure) ------------------
template <int WMW, int WNW, int TPB, bool RELU, bool ROUND, bool CVTA>
__global__ __launch_bounds__(TPB) void gemm_v2(
    int M, int N, int K,
    const float* __restrict__ A, const float* __restrict__ B,
    const float* __restrict__ bias,
    const float* __restrict__ D, const float* __restrict__ rowscale,
    float* __restrict__ C)
{
    constexpr int BM = WMW * 64, BN = WNW * 32, BK = 32;
    constexpr int AST = BK + 4;
    constexpr int BST = BN + 8;
    constexpr int ATILE = BM * AST;
    constexpr int BTILE = BK * BST;
    constexpr int CA = BM * BK / (4 * TPB);
    constexpr int CB = BK * BN / (4 * TPB);
    static_assert(CA >= 1 && CB >= 1, "tile/thread mismatch");
    static_assert(WMW * WNW * 32 == TPB, "warp layout mismatch");

    extern __shared__ float smem[];
    float* AsB = smem;
    float* BsB = smem + 2 * ATILE;

    int tid = threadIdx.x;
    int warp = tid >> 5, lane = tid & 31;
    int wm = warp / WNW, wn = warp % WNW;
    int lr = lane >> 2, lc = lane & 3;
    int block_m = blockIdx.y * BM, block_n = blockIdx.x * BN;

    float acc[4][4][4];
#pragma unroll
    for (int a = 0; a < 4; a++)
#pragma unroll
        for (int b = 0; b < 4; b++)
#pragma unroll
            for (int c = 0; c < 4; c++) acc[a][b][c] = 0.0f;

    auto load_tiles = [&](int it, float* As, float* Bs) {
#pragma unroll
        for (int i = 0; i < CA; i++) {
            int f = tid + TPB * i;
            int m = f >> 3, q = f & 7;
            int gr = block_m + m;
            uint32_t dst = (uint32_t)__cvta_generic_to_shared(As + m * AST + 4 * q);
            const float* src = A + (size_t)gr * K + it * BK + 4 * q;
            int sz = (gr < M) ? 16 : 0;
            asm volatile("cp.async.cg.shared.global [%0], [%1], 16, %2;"
                         :: "r"(dst), "l"(src), "r"(sz));
        }
#pragma unroll
        for (int i = 0; i < CB; i++) {
            int f = tid + TPB * i;
            int n4 = f % (BN / 4), k = f / (BN / 4);
            uint32_t dst = (uint32_t)__cvta_generic_to_shared(Bs + k * BST + 4 * n4);
            const float* src = B + (size_t)(it * BK + k) * N + block_n + 4 * n4;
            asm volatile("cp.async.cg.shared.global [%0], [%1], 16;"
                         :: "r"(dst), "l"(src));
        }
        asm volatile("cp.async.commit_group;");
    };

    int nIter = K / BK;
    load_tiles(0, AsB, BsB);

    for (int it = 0; it < nIter; ++it) {
        int buf = it & 1;
        if (it + 1 < nIter) {
            load_tiles(it + 1, AsB + (buf ^ 1) * ATILE, BsB + (buf ^ 1) * BTILE);
            asm volatile("cp.async.wait_group 1;");
        } else {
            asm volatile("cp.async.wait_group 0;");
        }
        __syncthreads();
        const float* As = AsB + buf * ATILE;
        const float* Bs = BsB + buf * BTILE;

#pragma unroll
        for (int ks = 0; ks < 4; ks++) {
            int col = ks * 8 + lc;
            uint32_t af[4][4], bfr[4][2];
#pragma unroll
            for (int mt = 0; mt < 4; mt++) {
                const float* ap = As + (wm * 64 + mt * 16 + lr) * AST + col;
                if (CVTA) {
                    af[mt][0] = tf32u(ap[0]);
                    af[mt][1] = tf32u(ap[8 * AST]);
                    af[mt][2] = tf32u(ap[4]);
                    af[mt][3] = tf32u(ap[8 * AST + 4]);
                } else {
                    af[mt][0] = __float_as_uint(ap[0]);
                    af[mt][1] = __float_as_uint(ap[8 * AST]);
                    af[mt][2] = __float_as_uint(ap[4]);
                    af[mt][3] = __float_as_uint(ap[8 * AST + 4]);
                }
            }
#pragma unroll
            for (int nt = 0; nt < 4; nt++) {
                const float* bp = Bs + col * BST + wn * 32 + nt * 8 + lr;
                bfr[nt][0] = __float_as_uint(bp[0]);
                bfr[nt][1] = __float_as_uint(bp[4 * BST]);
            }
#pragma unroll
            for (int mt = 0; mt < 4; mt++)
#pragma unroll
                for (int nt = 0; nt < 4; nt++)
                    asm volatile(
                        "mma.sync.aligned.m16n8k8.row.col.f32.tf32.tf32.f32 "
                        "{%0,%1,%2,%3}, {%4,%5,%6,%7}, {%8,%9}, {%0,%1,%2,%3};"
                        : "+f"(acc[mt][nt][0]), "+f"(acc[mt][nt][1]),
                          "+f"(acc[mt][nt][2]), "+f"(acc[mt][nt][3])
                        : "r"(af[mt][0]), "r"(af[mt][1]), "r"(af[mt][2]), "r"(af[mt][3]),
                          "r"(bfr[nt][0]), "r"(bfr[nt][1]));
        }
        __syncthreads();
    }

    // epilogue
#pragma unroll
    for (int mt = 0; mt < 4; mt++) {
#pragma unroll
        for (int half = 0; half < 2; half++) {
            int row = block_m + wm * 64 + mt * 16 + lr + half * 8;
            if (row >= M) continue;
            float rs = rowscale ? rowscale[row] : 1.0f;
#pragma unroll
            for (int nt = 0; nt < 4; nt++) {
                int gc = block_n + wn * 32 + nt * 8 + 2 * lc;
                float v0 = acc[mt][nt][half * 2 + 0];
                float v1 = acc[mt][nt][half * 2 + 1];
                if (D) {
                    float2 d = *(const float2*)(D + (size_t)row * N + gc);
                    v0 += d.x; v1 += d.y;
                }
                float b0 = 0.0f, b1 = 0.0f;
                if (bias) { b0 = bias[gc]; b1 = bias[gc + 1]; }
                v0 = rs * v0 + b0;
                v1 = rs * v1 + b1;
                if (RELU) { v0 = fmaxf(v0, 0.0f); v1 = fmaxf(v1, 0.0f); }
                if (ROUND) { v0 = tf32r(v0); v1 = tf32r(v1); }
                *(float2*)(C + (size_t)row * N + gc) = make_float2(v0, v1);
            }
        }
    }
}

constexpr size_t smem_bytes(int WMW, int WNW) {
    return (size_t)(2 * (WMW * 64) * 36 + 2 * 32 * (WNW * 32 + 8)) * 4;
}

// ---------------- edge kernel (c1 atomics + relu_s fp16 store) ---------------
__device__ __forceinline__ void red4(float* p, float4 v) {
    asm volatile("red.global.add.v4.f32 [%0], {%1,%2,%3,%4};"
                 :: "l"(p), "f"(v.x), "f"(v.y), "f"(v.z), "f"(v.w) : "memory");
}

__global__ __launch_bounds__(256) void edge_kernel(const int* __restrict__ en) {
    int wg = (blockIdx.x * blockDim.x + threadIdx.x) >> 5;
    int lane = threadIdx.x & 31;
    if (wg >= NEDGE) return;
    int v0 = en[wg * 3 + 0];
    int v1 = en[wg * 3 + 1];
    int v2 = en[wg * 3 + 2];
    float d0 = g_dscale[v0], d1 = g_dscale[v1], d2 = g_dscale[v2];

    if (lane < 16) {
        float4 a = *(const float4*)(g_emb_new + (size_t)v0 * RANK + lane * 4);
        float4 b = *(const float4*)(g_emb_new + (size_t)v1 * RANK + lane * 4);
        float4 c = *(const float4*)(g_emb_new + (size_t)v2 * RANK + lane * 4);
        a.x *= d0; a.y *= d0; a.z *= d0; a.w *= d0;
        b.x *= d1; b.y *= d1; b.z *= d1; b.w *= d1;
        c.x *= d2; c.y *= d2; c.z *= d2; c.w *= d2;
        float h0 = 0.5f * d0, h1 = 0.5f * d1, h2 = 0.5f * d2;
        float4 o0 = make_float4(h0 * b.x * c.x, h0 * b.y * c.y, h0 * b.z * c.z, h0 * b.w * c.w);
        float4 o1 = make_float4(h1 * a.x * c.x, h1 * a.y * c.y, h1 * a.z * c.z, h1 * a.w * c.w);
        float4 o2 = make_float4(h2 * a.x * b.x, h2 * a.y * b.y, h2 * a.z * b.z, h2 * a.w * b.w);
        red4(g_sum_c1 + (size_t)v0 * RANK + lane * 4, o0);
        red4(g_sum_c1 + (size_t)v1 * RANK + lane * 4, o1);
        red4(g_sum_c1 + (size_t)v2 * RANK + lane * 4, o2);
    }

    const float4* e0 = (const float4*)(g_emb2) + (size_t)v0 * (OUTD / 4);
    const float4* e1 = (const float4*)(g_emb2) + (size_t)v1 * (OUTD / 4);
    const float4* e2p = (const float4*)(g_emb2) + (size_t)v2 * (OUTD / 4);
    uint2* rout = (uint2*)(g_relu_s + (size_t)wg * OUTD);   // 4 halfs per uint2
#pragma unroll
    for (int t = 0; t < 2; t++) {
        int c4 = lane + t * 32;
        float4 x = e0[c4], y = e1[c4], z = e2p[c4];
        float4 s = make_float4(fmaxf(x.x + y.x + z.x, 0.0f),
                               fmaxf(x.y + y.y + z.y, 0.0f),
                               fmaxf(x.z + y.z + z.z, 0.0f),
                               fmaxf(x.w + y.w + z.w, 0.0f));
        __half2 hlo = __float22half2_rn(make_float2(s.x, s.y));
        __half2 hhi = __float22half2_rn(make_float2(s.z, s.w));
        uint2 pk;
        pk.x = *(uint32_t*)&hlo;
        pk.y = *(uint32_t*)&hhi;
        rout[c4] = pk;
    }
}

// ---------------- node gather: sum_s[v] = sum over incident edges ------------
__global__ __launch_bounds__(256) void gather_kernel() {
    int v = (blockIdx.x * blockDim.x + threadIdx.x) >> 5;
    int lane = threadIdx.x & 31;
    if (v >= N_NODES) return;
    int d = g_deg[v];
    if (d > CSRCAP) d = CSRCAP;
    float a[8];
#pragma unroll
    for (int q = 0; q < 8; q++) a[q] = 0.0f;
    for (int t = 0; t < d; t++) {
        int e = g_csr[v * CSRCAP + t];
        const uint4* r = (const uint4*)(g_relu_s + (size_t)e * OUTD);
        uint4 pk = r[lane];                       // 8 halfs
        __half2 h0 = *(__half2*)&pk.x;
        __half2 h1 = *(__half2*)&pk.y;
        __half2 h2 = *(__half2*)&pk.z;
        __half2 h3 = *(__half2*)&pk.w;
        float2 f0 = __half22float2(h0), f1 = __half22float2(h1);
        float2 f2 = __half22float2(h2), f3 = __half22float2(h3);
        a[0] += f0.x; a[1] += f0.y; a[2] += f1.x; a[3] += f1.y;
        a[4] += f2.x; a[5] += f2.y; a[6] += f3.x; a[7] += f3.y;
    }
    float4* o = (float4*)(g_sum_s + (size_t)v * OUTD);
    o[lane * 2]     = make_float4(a[0], a[1], a[2], a[3]);
    o[lane * 2 + 1] = make_float4(a[4], a[5], a[6], a[7]);
}

// ---------------- launch ----------------------------------------------------
extern "C" void kernel_launch(void* const* d_in, const int* in_sizes, int n_in,
                              void* d_out, int out_size) {
    const float* emb = (const float*)d_in[0];
    const int*   en  = (const int*)d_in[1];
    const float* Wp  = (const float*)d_in[2];
    const float* bp  = (const float*)d_in[3];
    const float* W2a = (const float*)d_in[4];
    const float* b2a = (const float*)d_in[5];
    const float* W2b = (const float*)d_in[6];
    const float* b2b = (const float*)d_in[7];
    const float* Wq  = (const float*)d_in[8];
    const float* bq  = (const float*)d_in[9];
    float* out = (float*)d_out;

    float *p_emb_new, *p_hid, *p_emb2, *p_sum_c1, *p_sum_s, *p_invdeg;
    float *p_emb_r, *p_wp_r, *p_w2a_r, *p_w2b_r, *p_wq_r, *p_bias1, *p_bias2;
    cudaGetSymbolAddress((void**)&p_emb_new, g_emb_new);
    cudaGetSymbolAddress((void**)&p_hid,     g_hid);
    cudaGetSymbolAddress((void**)&p_emb2,    g_emb2);
    cudaGetSymbolAddress((void**)&p_sum_c1,  g_sum_c1);
    cudaGetSymbolAddress((void**)&p_sum_s,   g_sum_s);
    cudaGetSymbolAddress((void**)&p_invdeg,  g_invdeg);
    cudaGetSymbolAddress((void**)&p_emb_r,   g_emb_r);
    cudaGetSymbolAddress((void**)&p_wp_r,    g_wp_r);
    cudaGetSymbolAddress((void**)&p_w2a_r,   g_w2a_r);
    cudaGetSymbolAddress((void**)&p_w2b_r,   g_w2b_r);
    cudaGetSymbolAddress((void**)&p_wq_r,    g_wq_r);
    cudaGetSymbolAddress((void**)&p_bias1,   g_bias1);
    cudaGetSymbolAddress((void**)&p_bias2,   g_bias2);

    constexpr size_t SM42 = smem_bytes(4, 2);   // 92160  (G1)
    constexpr size_t SM18 = smem_bytes(1, 8);   // 86016  (G2/G3/G4)
    cudaFuncSetAttribute(gemm_v2<4,2,256,false,false,false>, cudaFuncAttributeMaxDynamicSharedMemorySize, (int)SM42);
    cudaFuncSetAttribute(gemm_v2<1,8,256,true, true, false>, cudaFuncAttributeMaxDynamicSharedMemorySize, (int)SM18);
    cudaFuncSetAttribute(gemm_v2<1,8,256,false,false,false>, cudaFuncAttributeMaxDynamicSharedMemorySize, (int)SM18);
    cudaFuncSetAttribute(gemm_v2<1,8,256,true, false,true >, cudaFuncAttributeMaxDynamicSharedMemorySize, (int)SM18);

    const int M = N_NODES;

    // 1..3: prep  (slot 4 = G2 for the ncu window)
    {
        int total = FEAT * RANK + FEAT * HIDD + HIDD * OUTD + RANK * OUTD + RANK + HIDD;
        wprep_kernel<<<(total + 255) / 256, 256>>>(Wp, bp, W2a, b2a, W2b, Wq);  // 1
    }
    {
        int n4 = N_NODES * FEAT / 4;
        round_tf32_kernel<<<(n4 + 255) / 256, 256>>>((const float4*)emb, (float4*)p_emb_r, n4); // 2
    }
    zero_kernel<<<1024, 256>>>();                                   // 3

    // 4: G2: hid = round(relu(emb @ W2a + bias2))   [64x256, 256 thr]
    gemm_v2<1,8,256,true,true,false><<<dim3(HIDD / 256, (M + 63) / 64), 256, SM18>>>(
        M, HIDD, FEAT, p_emb_r, p_w2a_r, p_bias2, nullptr, nullptr, p_hid);
    // 5: G1: emb_new = emb @ Wp + bias1             [256x64, 256 thr]
    gemm_v2<4,2,256,false,false,false><<<dim3(1, (M + 255) / 256), 256, SM42>>>(
        M, RANK, FEAT, p_emb_r, p_wp_r, p_bias1, nullptr, nullptr, p_emb_new);
    // 6: G3: emb2 = hid @ W2b + b2b                 [64x256, 256 thr]
    gemm_v2<1,8,256,false,false,false><<<dim3(1, (M + 63) / 64), 256, SM18>>>(
        M, OUTD, HIDD, p_hid, p_w2b_r, b2b, nullptr, nullptr, p_emb2);
    // 7: CSR build (+degree)
    csr_kernel<<<(NEDGE * KE + 255) / 256, 256>>>(en);
    // 8: degree-derived scales
    scale_kernel<<<(N_NODES + 255) / 256, 256>>>();
    // 9: edge kernel: c1 atomics + relu_s fp16 store
    edge_kernel<<<(NEDGE * 32) / 256, 256>>>(en);
    // 10: node gather: sum_s
    gather_kernel<<<(N_NODES * 32 + 255) / 256, 256>>>();
    // 11: G4: out = relu(invdeg * (sum_c1 @ Wq + sum_s) + bq)  [CVTA]
    gemm_v2<1,8,256,true,false,true><<<dim3(1, (M + 63) / 64), 256, SM18>>>(
        M, OUTD, RANK, p_sum_c1, p_wq_r, bq, p_sum_s, p_invdeg, out);
}